// round 9
// baseline (speedup 1.0000x reference)
#include <cuda_runtime.h>
#include <math.h>

#define BATCH 2
#define NPTS 4096
#define MPTS 4096
#define NSTEPS 8
#define TOLER 1e-6f

#define TPB 128
#define MCH 256                     // targets per block tile (16 tiles)
#define GRID_BLKS 1024              // 2 batches * 32 n-chunks * 16 m-tiles
#define NGRP 32                     // arrival-tree groups (32 blocks each)

// ---------------- device state ----------------
__device__ float4 g_tgt4[BATCH * MPTS];             // (x,y,z,|t|^2)
__device__ unsigned long long g_scr[BATCH * NPTS];  // packed (orderable score | idx)
__device__ float g_Rcum[BATCH][9];
__device__ float g_tcum[BATCH][3];
__device__ float g_err[BATCH];
__device__ int g_done;
__device__ unsigned g_cnt1[NGRP * 32];              // group counters, 128B apart
__device__ unsigned g_cnt0;                         // root counter
__device__ unsigned g_flag[NGRP * 32];              // per-group release flags, 128B apart

// ---------------- init ----------------
__global__ void init_kernel(const float* __restrict__ ptgt) {
    int i = blockIdx.x * blockDim.x + threadIdx.x;  // 0..8191
    if (i < BATCH * MPTS) {
        float x = ptgt[i * 3 + 0];
        float y = ptgt[i * 3 + 1];
        float z = ptgt[i * 3 + 2];
        g_tgt4[i] = make_float4(x, y, z, x * x + y * y + z * z);
        g_scr[i] = 0xFFFFFFFFFFFFFFFFull;
    }
    if (i < NGRP * 32) { g_cnt1[i] = 0u; g_flag[i] = 0u; }
    if (i == 0) { g_done = 0; g_cnt0 = 0u; }
    if (i < BATCH) {
        g_err[i] = 0.0f;
        float* R = g_Rcum[i];
        R[0] = 1.f; R[1] = 0.f; R[2] = 0.f;
        R[3] = 0.f; R[4] = 1.f; R[5] = 0.f;
        R[6] = 0.f; R[7] = 0.f; R[8] = 1.f;
        g_tcum[i][0] = 0.f; g_tcum[i][1] = 0.f; g_tcum[i][2] = 0.f;
    }
}

// ---------------- float Horn quaternion Kabsch ----------------
__device__ __forceinline__ void matmul4(float* C, const float* A, const float* Bm) {
#pragma unroll
    for (int i = 0; i < 4; i++)
#pragma unroll
        for (int j = 0; j < 4; j++) {
            float a = 0.f;
#pragma unroll
            for (int k = 0; k < 4; k++) a = __fmaf_rn(A[i * 4 + k], Bm[k * 4 + j], a);
            C[i * 4 + j] = a;
        }
}

__device__ void solve_horn_f(const float* S, float* Rn, float* tn) {
    const float n = (float)NPTS;
    const float inv = 1.0f / n;
    const float pmx = S[0] * inv, pmy = S[1] * inv, pmz = S[2] * inv;
    const float qmx = S[3] * inv, qmy = S[4] * inv, qmz = S[5] * inv;

    const float Sxx = S[6]  - n * pmx * qmx, Sxy = S[7]  - n * pmx * qmy, Sxz = S[8]  - n * pmx * qmz;
    const float Syx = S[9]  - n * pmy * qmx, Syy = S[10] - n * pmy * qmy, Syz = S[11] - n * pmy * qmz;
    const float Szx = S[12] - n * pmz * qmx, Szy = S[13] - n * pmz * qmy, Szz = S[14] - n * pmz * qmz;

    float K[16];
    K[0]  = Sxx + Syy + Szz; K[1]  = Syz - Szy;        K[2]  = Szx - Sxz;       K[3]  = Sxy - Syx;
    K[5]  = Sxx - Syy - Szz; K[6]  = Sxy + Syx;        K[7]  = Szx + Sxz;
    K[10] = -Sxx + Syy - Szz; K[11] = Syz + Szy;
    K[15] = -Sxx - Syy + Szz;
    K[4] = K[1]; K[8] = K[2]; K[12] = K[3]; K[9] = K[6]; K[13] = K[7]; K[14] = K[11];

    float fro = 0.f;
#pragma unroll
    for (int i = 0; i < 16; i++) fro += K[i] * K[i];
    const float sc = rsqrtf(fro + 1e-30f);

    float Kf[16];
#pragma unroll
    for (int i = 0; i < 16; i++) Kf[i] = K[i] * sc;
    Kf[0] += 1.f; Kf[5] += 1.f; Kf[10] += 1.f; Kf[15] += 1.f;  // eigs in [0,2]

    float K2[16], K4[16];
    matmul4(K2, Kf, Kf);
    matmul4(K4, K2, K2);

    float v0 = 1.f, v1 = 0.02f, v2 = 0.03f, v3 = 0.04f;
#pragma unroll 4
    for (int it = 0; it < 48; it++) {
        float w0 = K4[0]  * v0 + K4[1]  * v1 + K4[2]  * v2 + K4[3]  * v3;
        float w1 = K4[4]  * v0 + K4[5]  * v1 + K4[6]  * v2 + K4[7]  * v3;
        float w2 = K4[8]  * v0 + K4[9]  * v1 + K4[10] * v2 + K4[11] * v3;
        float w3 = K4[12] * v0 + K4[13] * v1 + K4[14] * v2 + K4[15] * v3;
        if ((it & 3) == 3) {
            float r = rsqrtf(w0 * w0 + w1 * w1 + w2 * w2 + w3 * w3 + 1e-30f);
            w0 *= r; w1 *= r; w2 *= r; w3 *= r;
        }
        v0 = w0; v1 = w1; v2 = w2; v3 = w3;
    }

    const float qw = v0, qx = v1, qy = v2, qz = v3;
    const float nn = qw * qw + qx * qx + qy * qy + qz * qz;
    const float s2 = 2.0f / nn;
    Rn[0] = 1.f - s2 * (qy * qy + qz * qz); Rn[1] = s2 * (qx * qy - qw * qz); Rn[2] = s2 * (qx * qz + qw * qy);
    Rn[3] = s2 * (qx * qy + qw * qz); Rn[4] = 1.f - s2 * (qx * qx + qz * qz); Rn[5] = s2 * (qy * qz - qw * qx);
    Rn[6] = s2 * (qx * qz - qw * qy); Rn[7] = s2 * (qy * qz + qw * qx); Rn[8] = 1.f - s2 * (qx * qx + qy * qy);

    tn[0] = qmx - (Rn[0] * pmx + Rn[1] * pmy + Rn[2] * pmz);
    tn[1] = qmy - (Rn[3] * pmx + Rn[4] * pmy + Rn[5] * pmz);
    tn[2] = qmz - (Rn[6] * pmx + Rn[7] * pmy + Rn[8] * pmz);
}

// ---------------- critical tail: last-arriving block (128 threads) ----------------
__device__ void critical_tail(const float* __restrict__ psrc, float* __restrict__ out,
                              int step, int done0) {
    __shared__ float cRt[BATCH][12];
    __shared__ float c_part[4][16];
    __shared__ float c_S[BATCH][16];
    __shared__ float c_errnew[BATCH];
    __shared__ int c_done;

    const int tid = threadIdx.x;

    if (tid < 24) {
        int bb = tid / 12, j = tid - bb * 12;
        cRt[bb][j] = (j < 9) ? __ldcg(&g_Rcum[bb][j]) : __ldcg(&g_tcum[bb][j - 9]);
    }
    __syncthreads();

    float acc[16];
#pragma unroll
    for (int k = 0; k < 16; k++) acc[k] = 0.f;

    const int base = tid * 64;       // 64 contiguous points; warps 0-1 b0, 2-3 b1
    const int bb = tid >> 6;

    if (!done0) {
        const float R0 = cRt[bb][0], R1 = cRt[bb][1], R2 = cRt[bb][2];
        const float R3 = cRt[bb][3], R4 = cRt[bb][4], R5 = cRt[bb][5];
        const float R6 = cRt[bb][6], R7 = cRt[bb][7], R8 = cRt[bb][8];
        const float t0 = cRt[bb][9], t1 = cRt[bb][10], t2 = cRt[bb][11];

        for (int c = 0; c < 64; c += 8) {
            unsigned long long key[8];
#pragma unroll
            for (int i = 0; i < 8; i++) key[i] = __ldcg(&g_scr[base + c + i]);
#pragma unroll
            for (int i = 0; i < 8; i++) __stcg(&g_scr[base + c + i], 0xFFFFFFFFFFFFFFFFull);

            float4 q[8];
#pragma unroll
            for (int i = 0; i < 8; i++) {
                const int idx = ((int)(unsigned)(key[i] & 0xFFFFFFFFull)) & (MPTS - 1);
                q[i] = g_tgt4[(bb << 12) + idx];
            }
#pragma unroll
            for (int i = 0; i < 8; i++) {
                unsigned u = (unsigned)(key[i] >> 32);
                unsigned fb = (u & 0x80000000u) ? (u ^ 0x80000000u) : ~u;
                const float s = __uint_as_float(fb);

                const float* ps = psrc + (size_t)(base + c + i) * 3;
                const float x = __ldcg(&ps[0]), y = __ldcg(&ps[1]), z = __ldcg(&ps[2]);
                const float px = R0 * x + R1 * y + R2 * z + t0;
                const float py = R3 * x + R4 * y + R5 * z + t1;
                const float pz = R6 * x + R7 * y + R8 * z + t2;
                const float pn = px * px + py * py + pz * pz;
                const float dist = sqrtf(fmaxf(pn + s, 0.0f));

                acc[0] += px; acc[1] += py; acc[2] += pz;
                acc[3] += q[i].x; acc[4] += q[i].y; acc[5] += q[i].z;
                acc[6] += px * q[i].x; acc[7] += px * q[i].y; acc[8] += px * q[i].z;
                acc[9] += py * q[i].x; acc[10] += py * q[i].y; acc[11] += py * q[i].z;
                acc[12] += pz * q[i].x; acc[13] += pz * q[i].y; acc[14] += pz * q[i].z;
                acc[15] += dist;
            }
        }
    } else {
        for (int i = 0; i < 64; i++) __stcg(&g_scr[base + i], 0xFFFFFFFFFFFFFFFFull);
    }

    // fixed-order deterministic reduction
#pragma unroll
    for (int k = 0; k < 16; k++) {
        float a = acc[k];
        a += __shfl_down_sync(0xffffffffu, a, 16);
        a += __shfl_down_sync(0xffffffffu, a, 8);
        a += __shfl_down_sync(0xffffffffu, a, 4);
        a += __shfl_down_sync(0xffffffffu, a, 2);
        a += __shfl_down_sync(0xffffffffu, a, 1);
        acc[k] = a;
    }
    const int lane = tid & 31, warp = tid >> 5;
    if (lane == 0) {
#pragma unroll
        for (int k = 0; k < 16; k++) c_part[warp][k] = acc[k];
    }
    __syncthreads();
    if (tid < 32) {
        const int bsel = tid >> 4, k = tid & 15;
        float a = c_part[bsel * 2 + 0][k] + c_part[bsel * 2 + 1][k];
        c_S[bsel][k] = a;
        if (k == 15) c_errnew[bsel] = a / (float)NPTS;
    }
    __syncthreads();

    if (tid == 0) {
        int conv = (fabsf(c_errnew[0] - __ldcg(&g_err[0])) < TOLER) &&
                   (fabsf(c_errnew[1] - __ldcg(&g_err[1])) < TOLER);
        c_done = (done0 || conv) ? 1 : 0;
        __stcg(&g_done, c_done);
    }
    __syncthreads();

    if (tid < BATCH && !c_done) {
        float S[16];
#pragma unroll
        for (int k = 0; k < 16; k++) S[k] = c_S[tid][k];
        float Rn[9], tn[3];
        solve_horn_f(S, Rn, tn);

        float Ro[9], to[3];
#pragma unroll
        for (int i = 0; i < 9; i++) Ro[i] = cRt[tid][i];
#pragma unroll
        for (int i = 0; i < 3; i++) to[i] = cRt[tid][9 + i];

#pragma unroll
        for (int i = 0; i < 3; i++) {
#pragma unroll
            for (int j = 0; j < 3; j++) {
                float m = Rn[i * 3 + 0] * Ro[0 + j] + Rn[i * 3 + 1] * Ro[3 + j] +
                          Rn[i * 3 + 2] * Ro[6 + j];
                __stcg(&g_Rcum[tid][i * 3 + j], m);
            }
            float tm = Rn[i * 3 + 0] * to[0] + Rn[i * 3 + 1] * to[1] +
                       Rn[i * 3 + 2] * to[2] + tn[i];
            __stcg(&g_tcum[tid][i], tm);
        }
        __stcg(&g_err[tid], c_errnew[tid]);
        asm volatile("fence.acq_rel.gpu;" ::: "memory");   // publish solve writes
    }
    __syncthreads();

    if (step == NSTEPS - 1 && tid < BATCH) {
        float R[9];
#pragma unroll
        for (int i = 0; i < 9; i++) R[i] = __ldcg(&g_Rcum[tid][i]);
        out[tid * 7 + 0] = __ldcg(&g_tcum[tid][0]);
        out[tid * 7 + 1] = __ldcg(&g_tcum[tid][1]);
        out[tid * 7 + 2] = __ldcg(&g_tcum[tid][2]);
        const float r00 = R[0], r11 = R[4], r22 = R[8];
        float qw = 0.5f * sqrtf(fmaxf(1.f + r00 + r11 + r22, 1e-12f));
        float qx = 0.5f * sqrtf(fmaxf(1.f + r00 - r11 - r22, 1e-12f));
        float qy = 0.5f * sqrtf(fmaxf(1.f - r00 + r11 - r22, 1e-12f));
        float qz = 0.5f * sqrtf(fmaxf(1.f - r00 - r11 + r22, 1e-12f));
        qx = (R[7] - R[5] >= 0.f) ? qx : -qx;
        qy = (R[2] - R[6] >= 0.f) ? qy : -qy;
        qz = (R[3] - R[1] >= 0.f) ? qz : -qz;
        out[tid * 7 + 3] = qx;
        out[tid * 7 + 4] = qy;
        out[tid * 7 + 5] = qz;
        out[tid * 7 + 6] = qw;
    }
}

// ---------------- persistent ICP ----------------
__global__ __launch_bounds__(TPB, 8) void icp_kernel(const float* __restrict__ psrc,
                                                     float* __restrict__ out) {
    __shared__ float4 sh[MCH];
    __shared__ float sRt[12];
    __shared__ int s_ctrl[2];   // [0]=done, [1]=last

    const int tid = threadIdx.x;
    const int bx = blockIdx.x;
    const int b = bx >> 9;
    const int mtile = bx & 15;
    const int nchunk = (bx >> 4) & 31;
    const int mbase = mtile * MCH;
    const int n = nchunk * TPB + tid;
    const int gid = bx >> 5;    // arrival-tree group (32 blocks per group)

    // hoisted loop-invariants: target tile + source point
    for (int i = tid; i < MCH; i += TPB)
        sh[i] = g_tgt4[b * MPTS + mbase + i];

    const float* ps = psrc + ((size_t)b * NPTS + n) * 3;
    const float x = ps[0], y = ps[1], z = ps[2];
    unsigned long long* const scr = g_scr + (size_t)b * NPTS + n;

    for (int step = 0; step < NSTEPS; step++) {
        if (tid < 12)
            sRt[tid] = (tid < 9) ? __ldcg(&g_Rcum[b][tid]) : __ldcg(&g_tcum[b][tid - 9]);
        if (tid == 0) s_ctrl[0] = __ldcg(&g_done);
        __syncthreads();
        const int done0 = s_ctrl[0];

        if (!done0) {
            const float R0 = sRt[0], R1 = sRt[1], R2 = sRt[2];
            const float R3 = sRt[3], R4 = sRt[4], R5 = sRt[5];
            const float R6 = sRt[6], R7 = sRt[7], R8 = sRt[8];
            const float t0 = sRt[9], t1 = sRt[10], t2 = sRt[11];

            const float px = R0 * x + R1 * y + R2 * z + t0;
            const float py = R3 * x + R4 * y + R5 * z + t1;
            const float pz = R6 * x + R7 * y + R8 * z + t2;
            const float ax = -2.0f * px, ay = -2.0f * py, az = -2.0f * pz;

            float bs = 3.0e38f;
            int bi = 0;
#pragma unroll 8
            for (int m = 0; m < MCH; m++) {
                const float4 t = sh[m];       // warp-uniform broadcast
                float s = __fmaf_rn(ax, t.x, t.w);
                s = __fmaf_rn(ay, t.y, s);
                s = __fmaf_rn(az, t.z, s);
                if (s < bs) { bs = s; bi = m; }
            }

            unsigned u = __float_as_uint(bs);
            u = (u & 0x80000000u) ? ~u : (u | 0x80000000u);
            atomicMin(scr, ((unsigned long long)u << 32) | (unsigned)(mbase + bi));
        }
        __syncthreads();

        // ---- two-level arrival tree ----
        if (tid == 0) {
            s_ctrl[1] = 0;
            unsigned o1;
            asm volatile("atom.acq_rel.gpu.add.u32 %0, [%1], %2;"
                         : "=r"(o1) : "l"(&g_cnt1[gid * 32]), "r"(1u) : "memory");
            if (o1 == 31u) {
                unsigned o0;
                asm volatile("atom.acq_rel.gpu.add.u32 %0, [%1], %2;"
                             : "=r"(o0) : "l"(&g_cnt0), "r"(1u) : "memory");
                if (o0 == (unsigned)(NGRP - 1)) s_ctrl[1] = 1;
            }
        }
        __syncthreads();

        if (s_ctrl[1]) {
            critical_tail(psrc, out, step, done0);
            __syncthreads();
            if (tid == 0) {
                // reset counters BEFORE publishing flags (release chain orders them)
                __stcg(&g_cnt0, 0u);
#pragma unroll
                for (int g = 0; g < NGRP; g++) __stcg(&g_cnt1[g * 32], 0u);
#pragma unroll
                for (int g = 0; g < NGRP; g++)
                    asm volatile("st.release.gpu.u32 [%0], %1;"
                                 :: "l"(&g_flag[g * 32]), "r"((unsigned)(step + 1)) : "memory");
            }
        } else {
            if (tid == 0) {
                unsigned v;
                for (;;) {
                    asm volatile("ld.acquire.gpu.u32 %0, [%1];"
                                 : "=r"(v) : "l"(&g_flag[gid * 32]) : "memory");
                    if (v > (unsigned)step) break;
                    __nanosleep(64);
                }
            }
        }
        __syncthreads();
    }
}

// ---------------- launch ----------------
extern "C" void kernel_launch(void* const* d_in, const int* in_sizes, int n_in,
                              void* d_out, int out_size) {
    const float* psrc = (const float*)d_in[0];
    const float* ptgt = (const float*)d_in[1];
    float* out = (float*)d_out;

    init_kernel<<<(BATCH * MPTS + 255) / 256, 256>>>(ptgt);
    icp_kernel<<<GRID_BLKS, TPB>>>(psrc, out);
}

// round 10
// speedup vs baseline: 3.5293x; 3.5293x over previous
#include <cuda_runtime.h>
#include <math.h>

#define BATCH 2
#define NPTS 4096
#define MPTS 4096
#define NSTEPS 8
#define TOLER 1e-6f

#define TPB 128
#define MSPLIT 32
#define MCH 128                         // targets per nn tile (== TPB)
#define NCHB 32                         // n-chunks per batch (128 pts each)
#define NN_BLKS (BATCH * NCHB * MSPLIT) // 2048
#define TAIL_BLKS (BATCH * NCHB)        // 64
#define TOTAL_BLKS (NN_BLKS + TAIL_BLKS + 1)

// ---------------- device state ----------------
__device__ float4 g_tgt4[BATCH * MPTS];             // (x,y,z,|t|^2)
__device__ unsigned long long g_scr[BATCH * NPTS];  // packed (orderable score | idx)
__device__ float g_Rcum[BATCH][9];
__device__ float g_tcum[BATCH][3];
__device__ float g_err[BATCH];
__device__ int g_done;
__device__ unsigned g_cnt[TAIL_BLKS * 32];          // per-(b,nchunk) counters, 128B apart
__device__ unsigned g_tailcnt;
__device__ float g_part[TAIL_BLKS][16];

// ---------------- init ----------------
__global__ void init_kernel(const float* __restrict__ ptgt) {
    int i = blockIdx.x * blockDim.x + threadIdx.x;  // 0..8191
    if (i < BATCH * MPTS) {
        float x = ptgt[i * 3 + 0];
        float y = ptgt[i * 3 + 1];
        float z = ptgt[i * 3 + 2];
        g_tgt4[i] = make_float4(x, y, z, x * x + y * y + z * z);
        g_scr[i] = 0xFFFFFFFFFFFFFFFFull;
    }
    if (i < TAIL_BLKS * 32) g_cnt[i] = 0u;
    if (i == 0) { g_done = 0; g_tailcnt = 0u; }
    if (i < BATCH) {
        g_err[i] = 0.0f;
        float* R = g_Rcum[i];
        R[0] = 1.f; R[1] = 0.f; R[2] = 0.f;
        R[3] = 0.f; R[4] = 1.f; R[5] = 0.f;
        R[6] = 0.f; R[7] = 0.f; R[8] = 1.f;
        g_tcum[i][0] = 0.f; g_tcum[i][1] = 0.f; g_tcum[i][2] = 0.f;
    }
}

// ---------------- float Horn quaternion Kabsch ----------------
__device__ __forceinline__ void matmul4(float* C, const float* A, const float* Bm) {
#pragma unroll
    for (int i = 0; i < 4; i++)
#pragma unroll
        for (int j = 0; j < 4; j++) {
            float a = 0.f;
#pragma unroll
            for (int k = 0; k < 4; k++) a = __fmaf_rn(A[i * 4 + k], Bm[k * 4 + j], a);
            C[i * 4 + j] = a;
        }
}

__device__ void solve_horn_f(const float* S, float* Rn, float* tn) {
    const float n = (float)NPTS;
    const float inv = 1.0f / n;
    const float pmx = S[0] * inv, pmy = S[1] * inv, pmz = S[2] * inv;
    const float qmx = S[3] * inv, qmy = S[4] * inv, qmz = S[5] * inv;

    const float Sxx = S[6]  - n * pmx * qmx, Sxy = S[7]  - n * pmx * qmy, Sxz = S[8]  - n * pmx * qmz;
    const float Syx = S[9]  - n * pmy * qmx, Syy = S[10] - n * pmy * qmy, Syz = S[11] - n * pmy * qmz;
    const float Szx = S[12] - n * pmz * qmx, Szy = S[13] - n * pmz * qmy, Szz = S[14] - n * pmz * qmz;

    float K[16];
    K[0]  = Sxx + Syy + Szz; K[1]  = Syz - Szy;        K[2]  = Szx - Sxz;       K[3]  = Sxy - Syx;
    K[5]  = Sxx - Syy - Szz; K[6]  = Sxy + Syx;        K[7]  = Szx + Sxz;
    K[10] = -Sxx + Syy - Szz; K[11] = Syz + Szy;
    K[15] = -Sxx - Syy + Szz;
    K[4] = K[1]; K[8] = K[2]; K[12] = K[3]; K[9] = K[6]; K[13] = K[7]; K[14] = K[11];

    float fro = 0.f;
#pragma unroll
    for (int i = 0; i < 16; i++) fro += K[i] * K[i];
    const float sc = rsqrtf(fro + 1e-30f);

    float Kf[16];
#pragma unroll
    for (int i = 0; i < 16; i++) Kf[i] = K[i] * sc;
    Kf[0] += 1.f; Kf[5] += 1.f; Kf[10] += 1.f; Kf[15] += 1.f;  // eigs in [0,2]

    float K2[16], K4[16];
    matmul4(K2, Kf, Kf);
    matmul4(K4, K2, K2);

    float v0 = 1.f, v1 = 0.02f, v2 = 0.03f, v3 = 0.04f;
#pragma unroll 4
    for (int it = 0; it < 48; it++) {
        float w0 = K4[0]  * v0 + K4[1]  * v1 + K4[2]  * v2 + K4[3]  * v3;
        float w1 = K4[4]  * v0 + K4[5]  * v1 + K4[6]  * v2 + K4[7]  * v3;
        float w2 = K4[8]  * v0 + K4[9]  * v1 + K4[10] * v2 + K4[11] * v3;
        float w3 = K4[12] * v0 + K4[13] * v1 + K4[14] * v2 + K4[15] * v3;
        if ((it & 3) == 3) {
            float r = rsqrtf(w0 * w0 + w1 * w1 + w2 * w2 + w3 * w3 + 1e-30f);
            w0 *= r; w1 *= r; w2 *= r; w3 *= r;
        }
        v0 = w0; v1 = w1; v2 = w2; v3 = w3;
    }

    const float qw = v0, qx = v1, qy = v2, qz = v3;
    const float nn = qw * qw + qx * qx + qy * qy + qz * qz;
    const float s2 = 2.0f / nn;
    Rn[0] = 1.f - s2 * (qy * qy + qz * qz); Rn[1] = s2 * (qx * qy - qw * qz); Rn[2] = s2 * (qx * qz + qw * qy);
    Rn[3] = s2 * (qx * qy + qw * qz); Rn[4] = 1.f - s2 * (qx * qx + qz * qz); Rn[5] = s2 * (qy * qz - qw * qx);
    Rn[6] = s2 * (qx * qz - qw * qy); Rn[7] = s2 * (qy * qz + qw * qx); Rn[8] = 1.f - s2 * (qx * qx + qy * qy);

    tn[0] = qmx - (Rn[0] * pmx + Rn[1] * pmy + Rn[2] * pmz);
    tn[1] = qmy - (Rn[3] * pmx + Rn[4] * pmy + Rn[5] * pmz);
    tn[2] = qmz - (Rn[6] * pmx + Rn[7] * pmy + Rn[8] * pmz);
}

// ---------------- helpers ----------------
__device__ __forceinline__ void arrive(unsigned* p) {
    unsigned old;
    asm volatile("atom.acq_rel.gpu.global.add.u32 %0, [%1], %2;"
                 : "=r"(old) : "l"(p), "r"(1u) : "memory");
}
__device__ __forceinline__ void wait_ge(unsigned* p, unsigned target) {
    unsigned v;
    for (;;) {
        asm volatile("ld.acquire.gpu.global.u32 %0, [%1];"
                     : "=r"(v) : "l"(p) : "memory");
        if (v >= target) break;
        __nanosleep(32);
    }
}

// ---------------- one ICP step: NN -> tail reduce -> final solve, one launch ----------------
__global__ __launch_bounds__(TPB, 8) void step_kernel(const float* __restrict__ psrc,
                                                      float* __restrict__ out, int step) {
    const int tid = threadIdx.x;
    const int bx = blockIdx.x;

    // =================== NN blocks ===================
    if (bx < NN_BLKS) {
        __shared__ float4 sh[MCH];
        __shared__ float sRt[12];
        __shared__ int sdone;

        const int b = bx >> 10;
        const int mtile = bx & 31;
        const int nchunk = (bx >> 5) & 31;
        const int mbase = mtile * MCH;
        const int n = nchunk * TPB + tid;

        if (tid < 12)
            sRt[tid] = (tid < 9) ? g_Rcum[b][tid] : g_tcum[b][tid - 9];
        if (tid == 0) sdone = g_done;
        sh[tid] = g_tgt4[b * MPTS + mbase + tid];
        __syncthreads();

        if (!sdone) {
            const float R0 = sRt[0], R1 = sRt[1], R2 = sRt[2];
            const float R3 = sRt[3], R4 = sRt[4], R5 = sRt[5];
            const float R6 = sRt[6], R7 = sRt[7], R8 = sRt[8];
            const float t0 = sRt[9], t1 = sRt[10], t2 = sRt[11];

            const float* ps = psrc + ((size_t)b * NPTS + n) * 3;
            const float x = ps[0], y = ps[1], z = ps[2];
            const float px = R0 * x + R1 * y + R2 * z + t0;
            const float py = R3 * x + R4 * y + R5 * z + t1;
            const float pz = R6 * x + R7 * y + R8 * z + t2;
            const float ax = -2.0f * px, ay = -2.0f * py, az = -2.0f * pz;

            float bs = 3.0e38f;
            int bi = 0;
#pragma unroll 8
            for (int m = 0; m < MCH; m++) {
                const float4 t = sh[m];       // warp-uniform broadcast
                float s = __fmaf_rn(ax, t.x, t.w);
                s = __fmaf_rn(ay, t.y, s);
                s = __fmaf_rn(az, t.z, s);
                if (s < bs) { bs = s; bi = m; }
            }

            unsigned u = __float_as_uint(bs);
            u = (u & 0x80000000u) ? ~u : (u | 0x80000000u);
            atomicMin(g_scr + (size_t)b * NPTS + n,
                      ((unsigned long long)u << 32) | (unsigned)(mbase + bi));
        }
        __syncthreads();
        if (tid == 0) arrive(&g_cnt[(b * NCHB + nchunk) * 32]);
        return;
    }

    // =================== tail blocks ===================
    if (bx < NN_BLKS + TAIL_BLKS) {
        __shared__ float sRt[12];
        __shared__ int sdone;
        __shared__ float sm[4][16];

        const int t = bx - NN_BLKS;
        const int b = t >> 5;
        const int nchunk = t & 31;

        if (tid == 0) wait_ge(&g_cnt[t * 32], MSPLIT);
        if (tid < 12)
            sRt[tid] = (tid < 9) ? g_Rcum[b][tid] : g_tcum[b][tid - 9];
        if (tid == 1 % TPB) { }
        if (tid == 0) sdone = g_done;
        __syncthreads();

        const int p = b * NPTS + nchunk * TPB + tid;
        float v[16];
#pragma unroll
        for (int k = 0; k < 16; k++) v[k] = 0.f;

        const unsigned long long key = __ldcg(&g_scr[p]);
        __stcg(&g_scr[p], 0xFFFFFFFFFFFFFFFFull);   // re-arm for next step

        if (!sdone) {
            unsigned u = (unsigned)(key >> 32);
            unsigned fb = (u & 0x80000000u) ? (u ^ 0x80000000u) : ~u;
            const float s = __uint_as_float(fb);
            const int idx = ((int)(unsigned)(key & 0xFFFFFFFFull)) & (MPTS - 1);
            const float4 q = g_tgt4[(b << 12) + idx];

            const float* ps = psrc + (size_t)p * 3;
            const float x = ps[0], y = ps[1], z = ps[2];
            const float R0 = sRt[0], R1 = sRt[1], R2 = sRt[2];
            const float R3 = sRt[3], R4 = sRt[4], R5 = sRt[5];
            const float R6 = sRt[6], R7 = sRt[7], R8 = sRt[8];
            const float px = R0 * x + R1 * y + R2 * z + sRt[9];
            const float py = R3 * x + R4 * y + R5 * z + sRt[10];
            const float pz = R6 * x + R7 * y + R8 * z + sRt[11];
            const float pn = px * px + py * py + pz * pz;
            const float dist = sqrtf(fmaxf(pn + s, 0.0f));

            v[0] = px; v[1] = py; v[2] = pz;
            v[3] = q.x; v[4] = q.y; v[5] = q.z;
            v[6] = px * q.x; v[7] = px * q.y; v[8] = px * q.z;
            v[9] = py * q.x; v[10] = py * q.y; v[11] = py * q.z;
            v[12] = pz * q.x; v[13] = pz * q.y; v[14] = pz * q.z;
            v[15] = dist;
        }

        // fixed-order deterministic block reduction (4 warps)
#pragma unroll
        for (int k = 0; k < 16; k++) {
            float a = v[k];
            a += __shfl_down_sync(0xffffffffu, a, 16);
            a += __shfl_down_sync(0xffffffffu, a, 8);
            a += __shfl_down_sync(0xffffffffu, a, 4);
            a += __shfl_down_sync(0xffffffffu, a, 2);
            a += __shfl_down_sync(0xffffffffu, a, 1);
            v[k] = a;
        }
        const int lane = tid & 31, warp = tid >> 5;
        if (lane == 0) {
#pragma unroll
            for (int k = 0; k < 16; k++) sm[warp][k] = v[k];
        }
        __syncthreads();
        if (tid < 16) {
            float a = sm[0][tid] + sm[1][tid] + sm[2][tid] + sm[3][tid];
            __stcg(&g_part[t][tid], a);
        }
        __syncthreads();
        if (tid == 0) arrive(&g_tailcnt);
        return;
    }

    // =================== final block ===================
    {
        __shared__ float cRt[BATCH][12];
        __shared__ float c_S[BATCH][16];
        __shared__ float c_errnew[BATCH];
        __shared__ int c_done, c_done0;

        if (tid == 0) { wait_ge(&g_tailcnt, TAIL_BLKS); c_done0 = g_done; }
        __syncthreads();
        const int done0 = c_done0;

        if (tid < 24) {
            int bb = tid / 12, j = tid - bb * 12;
            cRt[bb][j] = (j < 9) ? g_Rcum[bb][j] : g_tcum[bb][j - 9];
        }
        __syncthreads();

        if (tid < 32) {
            const int bsel = tid >> 4, k = tid & 15;
            float a = 0.f;
#pragma unroll
            for (int c = 0; c < NCHB; c++)             // fixed order: deterministic
                a += __ldcg(&g_part[bsel * NCHB + c][k]);
            c_S[bsel][k] = a;
            if (k == 15) c_errnew[bsel] = a / (float)NPTS;
        }
        __syncthreads();

        if (tid == 0) {
            int conv = (fabsf(c_errnew[0] - g_err[0]) < TOLER) &&
                       (fabsf(c_errnew[1] - g_err[1]) < TOLER);
            c_done = (done0 || conv) ? 1 : 0;
            __stcg(&g_done, c_done);
        }
        __syncthreads();

        if (tid < BATCH && !c_done) {
            float S[16];
#pragma unroll
            for (int k = 0; k < 16; k++) S[k] = c_S[tid][k];
            float Rn[9], tn[3];
            solve_horn_f(S, Rn, tn);

            float Ro[9], to[3];
#pragma unroll
            for (int i = 0; i < 9; i++) Ro[i] = cRt[tid][i];
#pragma unroll
            for (int i = 0; i < 3; i++) to[i] = cRt[tid][9 + i];

#pragma unroll
            for (int i = 0; i < 3; i++) {
#pragma unroll
                for (int j = 0; j < 3; j++) {
                    float m = Rn[i * 3 + 0] * Ro[0 + j] + Rn[i * 3 + 1] * Ro[3 + j] +
                              Rn[i * 3 + 2] * Ro[6 + j];
                    __stcg(&g_Rcum[tid][i * 3 + j], m);
                }
                float tm = Rn[i * 3 + 0] * to[0] + Rn[i * 3 + 1] * to[1] +
                           Rn[i * 3 + 2] * to[2] + tn[i];
                __stcg(&g_tcum[tid][i], tm);
            }
            __stcg(&g_err[tid], c_errnew[tid]);
        }
        __syncthreads();

        // reset counters for next step kernel (kernel boundary orders visibility)
        for (int i = tid; i < TAIL_BLKS * 32; i += TPB) __stcg(&g_cnt[i], 0u);
        if (tid == 0) __stcg(&g_tailcnt, 0u);

        if (step == NSTEPS - 1 && tid < BATCH) {
            float R[9];
#pragma unroll
            for (int i = 0; i < 9; i++) R[i] = __ldcg(&g_Rcum[tid][i]);
            out[tid * 7 + 0] = __ldcg(&g_tcum[tid][0]);
            out[tid * 7 + 1] = __ldcg(&g_tcum[tid][1]);
            out[tid * 7 + 2] = __ldcg(&g_tcum[tid][2]);
            const float r00 = R[0], r11 = R[4], r22 = R[8];
            float qw = 0.5f * sqrtf(fmaxf(1.f + r00 + r11 + r22, 1e-12f));
            float qx = 0.5f * sqrtf(fmaxf(1.f + r00 - r11 - r22, 1e-12f));
            float qy = 0.5f * sqrtf(fmaxf(1.f - r00 + r11 - r22, 1e-12f));
            float qz = 0.5f * sqrtf(fmaxf(1.f - r00 - r11 + r22, 1e-12f));
            qx = (R[7] - R[5] >= 0.f) ? qx : -qx;
            qy = (R[2] - R[6] >= 0.f) ? qy : -qy;
            qz = (R[3] - R[1] >= 0.f) ? qz : -qz;
            out[tid * 7 + 3] = qx;
            out[tid * 7 + 4] = qy;
            out[tid * 7 + 5] = qz;
            out[tid * 7 + 6] = qw;
        }
    }
}

// ---------------- launch ----------------
extern "C" void kernel_launch(void* const* d_in, const int* in_sizes, int n_in,
                              void* d_out, int out_size) {
    const float* psrc = (const float*)d_in[0];
    const float* ptgt = (const float*)d_in[1];
    float* out = (float*)d_out;

    init_kernel<<<(BATCH * MPTS + 255) / 256, 256>>>(ptgt);
    for (int s = 0; s < NSTEPS; s++)
        step_kernel<<<TOTAL_BLKS, TPB>>>(psrc, out, s);
}